// round 10
// baseline (speedup 1.0000x reference)
#include <cuda_runtime.h>
#include <math_constants.h>

// VectorQuantizer — bit-exact replication of the jax-CPU (XLA/Eigen) reference.
//   dot   : sequential FMA chain over k=0..63, from 0
//   zsq   : scalar sequential rnd(mul)+rnd(add) over k=0..63
//   csq   : scalar sequential rnd(mul)+rnd(add) over k=0..63
//   dist  : rnd( rnd(zsq - 2*dot) + csq )
//   argmin: strict <, ascending code index (first-min tie-break)
//   out   : rnd( z + rnd(q - z) )
// fma.rn.f32x2 = two independent fma.rn lanes -> two codes per register.
// R7 change: prefetch depth 2 (C/D/N rotation). R6's 1-deep pipeline gave
// load-use distance ~24cyc < LDS lat 29cyc -> per-iteration stalls at 2
// warps/SMSP (issue=31.8%). Depth 2 -> ~45cyc distance, fully covered.

#define NROWS   65536
#define DIM     64
#define NCODES  1024
#define CHUNK   256
#define NCHUNKS (NCODES / CHUNK)
#define TPB     128
#define NBLOCKS (NROWS / TPB)

// dyn smem: pair-interleaved codes ((CHUNK/2)*DIM u64 = 64KB) + csq + idx
#define SMEM_BYTES ((CHUNK/2)*DIM*8 + CHUNK*4 + TPB*4)

typedef unsigned long long u64;

__device__ u64          g_accum = 0;   // fixed-point 2^-40 loss accumulator
__device__ unsigned int g_done  = 0;   // blocks-finished counter

__device__ __forceinline__ void fma2(u64& d, u64 a, u64 b) {
    asm("fma.rn.f32x2 %0, %1, %2, %0;" : "+l"(d) : "l"(a), "l"(b));
}
__device__ __forceinline__ u64 pack2(float x, float y) {
    u64 r; asm("mov.b64 %0, {%1, %2};" : "=l"(r) : "f"(x), "f"(y)); return r;
}
__device__ __forceinline__ float2 unpack2(u64 v) {
    float2 f; asm("mov.b64 {%0, %1}, %2;" : "=f"(f.x), "=f"(f.y) : "l"(v)); return f;
}

__global__ __launch_bounds__(TPB, 2) void vq_fused_kernel(
    const float* __restrict__ z,
    const float* __restrict__ emb,
    float* __restrict__ out,
    int out_size)
{
    extern __shared__ u64 sm_pairs[];                       // (CHUNK/2)*DIM u64
    float* s_c   = (float*)(sm_pairs + (CHUNK / 2) * DIM);  // CHUNK
    int*   s_idx = (int*)(s_c + CHUNK);                     // TPB

    const int tid = threadIdx.x;
    const int row = blockIdx.x * TPB + tid;

    // Load z row; zsq = sequential scalar mul+add (reference order);
    // zz[k] = {z_k, z_k} packed for dual-code f32x2 chains.
    float zsq = 0.f;
    u64 zz[DIM];
    {
        const float4* zp = (const float4*)(z + (size_t)row * DIM);
#pragma unroll
        for (int i = 0; i < DIM / 4; i++) {
            float4 v = zp[i];
            zsq = __fadd_rn(zsq, __fmul_rn(v.x, v.x));
            zsq = __fadd_rn(zsq, __fmul_rn(v.y, v.y));
            zsq = __fadd_rn(zsq, __fmul_rn(v.z, v.z));
            zsq = __fadd_rn(zsq, __fmul_rn(v.w, v.w));
            zz[4 * i + 0] = pack2(v.x, v.x);
            zz[4 * i + 1] = pack2(v.y, v.y);
            zz[4 * i + 2] = pack2(v.z, v.z);
            zz[4 * i + 3] = pack2(v.w, v.w);
        }
    }

    float best = CUDART_INF_F;
    int   bidx = 0;

    for (int ch = 0; ch < NCHUNKS; ch++) {
        // Stage chunk pair-interleaved: s_pairs[p*DIM+k] = {e[2p][k], e[2p+1][k]}
        {
            const float2* src = (const float2*)(emb + (size_t)ch * CHUNK * DIM);
            float* s32 = (float*)sm_pairs;
            for (int idx = tid; idx < CHUNK * DIM / 2; idx += TPB) {
                int c  = idx >> 5;            // code within chunk (32 float2/code)
                int kq = idx & 31;
                float2 e2 = src[c * 32 + kq];
                int p = c >> 1, l = c & 1;
                s32[((p * DIM + 2 * kq)     << 1) + l] = e2.x;
                s32[((p * DIM + 2 * kq + 1) << 1) + l] = e2.y;
            }
            // csq for this chunk: 2 codes/thread, exact sequential chain (L2-hot).
#pragma unroll
            for (int cc = 0; cc < CHUNK / TPB; cc++) {
                int c = cc * TPB + tid;
                const float4* e4 = (const float4*)(emb + ((size_t)ch * CHUNK + c) * DIM);
                float acc = 0.f;
#pragma unroll
                for (int i = 0; i < DIM / 4; i++) {
                    float4 v = e4[i];
                    acc = __fadd_rn(acc, __fmul_rn(v.x, v.x));
                    acc = __fadd_rn(acc, __fmul_rn(v.y, v.y));
                    acc = __fadd_rn(acc, __fmul_rn(v.z, v.z));
                    acc = __fadd_rn(acc, __fmul_rn(v.w, v.w));
                }
                s_c[c] = acc;
            }
        }
        __syncthreads();

        for (int p0 = 0; p0 < CHUNK / 2; p0 += 4) {     // 4 pairs = 8 codes in flight
            const u64* e0 = sm_pairs + (size_t)(p0 + 0) * DIM;
            const u64* e1 = sm_pairs + (size_t)(p0 + 1) * DIM;
            const u64* e2 = sm_pairs + (size_t)(p0 + 2) * DIM;
            const u64* e3 = sm_pairs + (size_t)(p0 + 3) * DIM;
            u64 a0 = 0ull, a1 = 0ull, a2 = 0ull, a3 = 0ull;
            // Depth-2 software pipeline: C = data for k, D = k+2, N = k+4.
            ulonglong2 C0 = *(const ulonglong2*)(e0);
            ulonglong2 C1 = *(const ulonglong2*)(e1);
            ulonglong2 C2 = *(const ulonglong2*)(e2);
            ulonglong2 C3 = *(const ulonglong2*)(e3);
            ulonglong2 D0 = *(const ulonglong2*)(e0 + 2);
            ulonglong2 D1 = *(const ulonglong2*)(e1 + 2);
            ulonglong2 D2 = *(const ulonglong2*)(e2 + 2);
            ulonglong2 D3 = *(const ulonglong2*)(e3 + 2);
#pragma unroll
            for (int k = 0; k < DIM; k += 2) {
                ulonglong2 N0, N1, N2, N3;
                if (k + 4 < DIM) {
                    N0 = *(const ulonglong2*)(e0 + k + 4);
                    N1 = *(const ulonglong2*)(e1 + k + 4);
                    N2 = *(const ulonglong2*)(e2 + k + 4);
                    N3 = *(const ulonglong2*)(e3 + k + 4);
                }
                fma2(a0, zz[k],     C0.x);  fma2(a1, zz[k],     C1.x);
                fma2(a2, zz[k],     C2.x);  fma2(a3, zz[k],     C3.x);
                fma2(a0, zz[k + 1], C0.y);  fma2(a1, zz[k + 1], C1.y);
                fma2(a2, zz[k + 1], C2.y);  fma2(a3, zz[k + 1], C3.y);
                if (k + 2 < DIM) { C0 = D0; C1 = D1; C2 = D2; C3 = D3; }
                if (k + 4 < DIM) { D0 = N0; D1 = N1; D2 = N2; D3 = N3; }
            }
            float2 d0 = unpack2(a0), d1 = unpack2(a1);
            float2 d2 = unpack2(a2), d3 = unpack2(a3);
            const int cl = p0 * 2;                 // local code base
            const int cg = ch * CHUNK + cl;        // global code base
            float dots[8] = {d0.x, d0.y, d1.x, d1.y, d2.x, d2.y, d3.x, d3.y};
#pragma unroll
            for (int j = 0; j < 8; j++) {          // ascending index: first-min ties
                float t    = __fadd_rn(zsq, __fmul_rn(dots[j], -2.0f));
                float dist = __fadd_rn(t, s_c[cl + j]);
                if (dist < best) { best = dist; bidx = cg + j; }
            }
        }
        __syncthreads();
    }

    s_idx[tid] = bidx;
    __syncthreads();

    // Output pass: out = rnd(z + rnd(q - z)); loss partial in double.
    double lsum = 0.0;
    {
        const float4* zb = (const float4*)(z + (size_t)blockIdx.x * TPB * DIM);
        const float4* eb = (const float4*)emb;
        float4* ob = (float4*)out + (size_t)blockIdx.x * TPB * (DIM / 4);
        for (int idx = tid; idx < TPB * (DIM / 4); idx += TPB) {
            int r  = idx >> 4;
            int c4 = idx & 15;
            float4 zv = zb[idx];
            float4 qv = eb[(size_t)s_idx[r] * (DIM / 4) + c4];
            float4 dv, ov;
            dv.x = __fadd_rn(qv.x, -zv.x);  ov.x = __fadd_rn(zv.x, dv.x);
            dv.y = __fadd_rn(qv.y, -zv.y);  ov.y = __fadd_rn(zv.y, dv.y);
            dv.z = __fadd_rn(qv.z, -zv.z);  ov.z = __fadd_rn(zv.z, dv.z);
            dv.w = __fadd_rn(qv.w, -zv.w);  ov.w = __fadd_rn(zv.w, dv.w);
            lsum += (double)__fmul_rn(dv.x, dv.x) + (double)__fmul_rn(dv.y, dv.y)
                  + (double)__fmul_rn(dv.z, dv.z) + (double)__fmul_rn(dv.w, dv.w);
            ob[idx] = ov;
        }
    }
    // Deterministic block reduce (double), then one exact fixed-point atomic.
    __shared__ double s_red[TPB / 32];
#pragma unroll
    for (int o = 16; o > 0; o >>= 1)
        lsum += __shfl_down_sync(0xffffffffu, lsum, o);
    if ((tid & 31) == 0) s_red[tid >> 5] = lsum;
    __syncthreads();
    if (tid == 0) {
        double t = 0.0;
#pragma unroll
        for (int i = 0; i < TPB / 32; i++) t += s_red[i];
        // fixed point: 2^40 scale; block total ~8200 -> ~9e15; x512 < 2^63. exact.
        u64 q = (u64)(t * 1099511627776.0 + 0.5);
        atomicAdd(&g_accum, q);
        __threadfence();
        unsigned int done = atomicAdd(&g_done, 1u);
        if (done == NBLOCKS - 1) {                // last block finalizes
            u64 total = *(volatile u64*)&g_accum; // all adds visible (fence+atomic)
            double s = (double)total * (1.0 / 1099511627776.0);
            float mf = (float)(s / (double)((size_t)NROWS * DIM));
            out[out_size - 1] = __fadd_rn(__fmul_rn(0.25f, mf), mf);
            *(volatile u64*)&g_accum = 0ull;      // reset for next (graph) call
            *(volatile unsigned int*)&g_done = 0u;
        }
    }
}

extern "C" void kernel_launch(void* const* d_in, const int* in_sizes, int n_in,
                              void* d_out, int out_size) {
    const float* z   = (const float*)d_in[0];
    const float* emb = (const float*)d_in[1];
    if (n_in >= 2 && in_sizes[0] == NCODES * DIM && in_sizes[1] == NROWS * DIM) {
        const float* t = z; z = emb; emb = t;   // defensive order check
    }
    float* out = (float*)d_out;

    cudaFuncSetAttribute(vq_fused_kernel,
                         cudaFuncAttributeMaxDynamicSharedMemorySize, SMEM_BYTES);

    vq_fused_kernel<<<NBLOCKS, TPB, SMEM_BYTES>>>(z, emb, out, out_size);
}

// round 12
// speedup vs baseline: 1.5422x; 1.5422x over previous
#include <cuda_runtime.h>
#include <math_constants.h>

// VectorQuantizer — bit-exact replication of the jax-CPU (XLA/Eigen) reference.
//   dot   : sequential FMA chain over k=0..63, from 0      (per row,code)
//   zsq   : scalar sequential rnd(mul)+rnd(add) k ascending
//   csq   : scalar sequential rnd(mul)+rnd(add) k ascending
//   dist  : rnd( rnd(zsq - 2*dot) + csq )
//   argmin: strict <, ascending code index (first-min tie-break)
//   out   : rnd( z + rnd(q - z) )
//
// R8: ROW-PAIRED f32x2. zz[k] = {zA[k], zB[k]} (2 rows/thread, 128 regs —
// same cost as R7's wasteful {z,z} duplication). e-operand duplicated per-use
// via mov.b64 {e,e} on the idle ALU pipe. Halves broadcast LDS.128 traffic
// per row (R7 was L1tex-wavefront bound at 72.5%), halves thread count ->
// 256 blocks = single wave (kills the 1.73-wave tail). Codebook staged
// transposed e_T[k][c] by a prep kernel (also computes csq).

#define NROWS   65536
#define DIM     64
#define NCODES  1024
#define CHUNK   256
#define NCHUNKS (NCODES / CHUNK)
#define TPB     128
#define ROWS_PER_BLOCK (2 * TPB)
#define NBLOCKS (NROWS / ROWS_PER_BLOCK)   // 256

// dyn smem: transposed codes e_T[k][c] (DIM*CHUNK f = 64KB) + csq + idx
#define SMEM_BYTES (DIM*CHUNK*4 + CHUNK*4 + ROWS_PER_BLOCK*4)

typedef unsigned long long u64;

__device__ float        g_eT[DIM * NCODES];   // transposed codebook [k][c]
__device__ float        g_ctable[NCODES];     // ||e_c||^2 exact chains
__device__ u64          g_accum = 0;          // fixed-point 2^-40 loss accum
__device__ unsigned int g_done  = 0;

__device__ __forceinline__ void fma2(u64& d, u64 a, u64 b) {
    asm("fma.rn.f32x2 %0, %1, %2, %0;" : "+l"(d) : "l"(a), "l"(b));
}
__device__ __forceinline__ u64 pack2(float x, float y) {
    u64 r; asm("mov.b64 %0, {%1, %2};" : "=l"(r) : "f"(x), "f"(y)); return r;
}
__device__ __forceinline__ u64 dup2(float x) {
    u64 r; asm("mov.b64 %0, {%1, %1};" : "=l"(r) : "f"(x)); return r;
}
__device__ __forceinline__ float2 unpack2(u64 v) {
    float2 f; asm("mov.b64 {%0, %1}, %2;" : "=f"(f.x), "=f"(f.y) : "l"(v)); return f;
}

// Prep: transpose codebook into g_eT[k][c] and build exact csq table.
__global__ void vq_prep_kernel(const float* __restrict__ emb) {
    int c = blockIdx.x * blockDim.x + threadIdx.x;
    if (c < NCODES) {
        const float4* e4 = (const float4*)(emb + (size_t)c * DIM);
        float acc = 0.f;
#pragma unroll
        for (int i = 0; i < DIM / 4; i++) {
            float4 v = e4[i];
            acc = __fadd_rn(acc, __fmul_rn(v.x, v.x));
            acc = __fadd_rn(acc, __fmul_rn(v.y, v.y));
            acc = __fadd_rn(acc, __fmul_rn(v.z, v.z));
            acc = __fadd_rn(acc, __fmul_rn(v.w, v.w));
            g_eT[(4 * i + 0) * NCODES + c] = v.x;
            g_eT[(4 * i + 1) * NCODES + c] = v.y;
            g_eT[(4 * i + 2) * NCODES + c] = v.z;
            g_eT[(4 * i + 3) * NCODES + c] = v.w;
        }
        g_ctable[c] = acc;
    }
}

__global__ __launch_bounds__(TPB, 2) void vq_main_kernel(
    const float* __restrict__ z,
    const float* __restrict__ emb,
    float* __restrict__ out,
    int out_size)
{
    extern __shared__ float sE[];                 // [DIM][CHUNK] transposed
    float* s_c   = sE + DIM * CHUNK;              // CHUNK
    int*   s_idx = (int*)(s_c + CHUNK);           // ROWS_PER_BLOCK

    const int tid = threadIdx.x;
    const int rowA = blockIdx.x * ROWS_PER_BLOCK + tid;
    const int rowB = rowA + TPB;

    // Load 2 rows; exact zsq chains; zz[k] = {zA[k], zB[k]}.
    float zsqA = 0.f, zsqB = 0.f;
    u64 zz[DIM];
    {
        const float4* pa = (const float4*)(z + (size_t)rowA * DIM);
        const float4* pb = (const float4*)(z + (size_t)rowB * DIM);
#pragma unroll
        for (int i = 0; i < DIM / 4; i++) {
            float4 a = pa[i], b = pb[i];
            zsqA = __fadd_rn(zsqA, __fmul_rn(a.x, a.x));
            zsqA = __fadd_rn(zsqA, __fmul_rn(a.y, a.y));
            zsqA = __fadd_rn(zsqA, __fmul_rn(a.z, a.z));
            zsqA = __fadd_rn(zsqA, __fmul_rn(a.w, a.w));
            zsqB = __fadd_rn(zsqB, __fmul_rn(b.x, b.x));
            zsqB = __fadd_rn(zsqB, __fmul_rn(b.y, b.y));
            zsqB = __fadd_rn(zsqB, __fmul_rn(b.z, b.z));
            zsqB = __fadd_rn(zsqB, __fmul_rn(b.w, b.w));
            zz[4 * i + 0] = pack2(a.x, b.x);
            zz[4 * i + 1] = pack2(a.y, b.y);
            zz[4 * i + 2] = pack2(a.z, b.z);
            zz[4 * i + 3] = pack2(a.w, b.w);
        }
    }

    float bestA = CUDART_INF_F, bestB = CUDART_INF_F;
    int   bidxA = 0, bidxB = 0;

    for (int ch = 0; ch < NCHUNKS; ch++) {
        // Stage transposed chunk: sE[k][c] = g_eT[k][ch*CHUNK + c].
        // Coalesced LDG float4, conflict-free STS float4.
        {
            const int c0 = ch * CHUNK;
            for (int idx = tid; idx < DIM * (CHUNK / 4); idx += TPB) {
                int k  = idx >> 6;              // CHUNK/4 = 64 float4 per k-row
                int c4 = idx & 63;
                ((float4*)sE)[k * (CHUNK / 4) + c4] =
                    ((const float4*)(g_eT + (size_t)k * NCODES + c0))[c4];
            }
            for (int c = tid; c < CHUNK; c += TPB)
                s_c[c] = g_ctable[ch * CHUNK + c];
        }
        __syncthreads();

        // 4 codes per group; one broadcast LDS.128 per k serves 4 codes x 2 rows.
        for (int g = 0; g < CHUNK / 4; g++) {
            const float4* col = (const float4*)sE + g;   // [k][4g..4g+3] at k*64+g
            u64 a0 = 0ull, a1 = 0ull, a2 = 0ull, a3 = 0ull;
            float4 cur[4], nxt[4];
#pragma unroll
            for (int j = 0; j < 4; j++) cur[j] = col[j * (CHUNK / 4)];
#pragma unroll
            for (int k4 = 0; k4 < DIM / 4; k4++) {
                if (k4 + 1 < DIM / 4) {
#pragma unroll
                    for (int j = 0; j < 4; j++)
                        nxt[j] = col[(4 * (k4 + 1) + j) * (CHUNK / 4)];
                }
#pragma unroll
                for (int j = 0; j < 4; j++) {
                    const int k = 4 * k4 + j;
                    float4 v = cur[j];
                    fma2(a0, zz[k], dup2(v.x));
                    fma2(a1, zz[k], dup2(v.y));
                    fma2(a2, zz[k], dup2(v.z));
                    fma2(a3, zz[k], dup2(v.w));
                }
                if (k4 + 1 < DIM / 4) {
#pragma unroll
                    for (int j = 0; j < 4; j++) cur[j] = nxt[j];
                }
            }
            float2 d0 = unpack2(a0), d1 = unpack2(a1);
            float2 d2 = unpack2(a2), d3 = unpack2(a3);
            const int cl = 4 * g;                  // local code base
            const int cg = ch * CHUNK + cl;        // global code base
            float dA[4] = {d0.x, d1.x, d2.x, d3.x};
            float dB[4] = {d0.y, d1.y, d2.y, d3.y};
#pragma unroll
            for (int j = 0; j < 4; j++) {          // ascending: first-min ties
                float csq = s_c[cl + j];
                float tA = __fadd_rn(zsqA, __fmul_rn(dA[j], -2.0f));
                float distA = __fadd_rn(tA, csq);
                if (distA < bestA) { bestA = distA; bidxA = cg + j; }
                float tB = __fadd_rn(zsqB, __fmul_rn(dB[j], -2.0f));
                float distB = __fadd_rn(tB, csq);
                if (distB < bestB) { bestB = distB; bidxB = cg + j; }
            }
        }
        __syncthreads();
    }

    s_idx[tid]       = bidxA;
    s_idx[TPB + tid] = bidxB;
    __syncthreads();

    // Output pass: out = rnd(z + rnd(q - z)); loss partial in double.
    double lsum = 0.0;
    {
        const float4* zb = (const float4*)(z + (size_t)blockIdx.x * ROWS_PER_BLOCK * DIM);
        const float4* eb = (const float4*)emb;
        float4* ob = (float4*)out + (size_t)blockIdx.x * ROWS_PER_BLOCK * (DIM / 4);
        for (int idx = tid; idx < ROWS_PER_BLOCK * (DIM / 4); idx += TPB) {
            int r  = idx >> 4;
            int c4 = idx & 15;
            float4 zv = zb[idx];
            float4 qv = eb[(size_t)s_idx[r] * (DIM / 4) + c4];
            float4 dv, ov;
            dv.x = __fadd_rn(qv.x, -zv.x);  ov.x = __fadd_rn(zv.x, dv.x);
            dv.y = __fadd_rn(qv.y, -zv.y);  ov.y = __fadd_rn(zv.y, dv.y);
            dv.z = __fadd_rn(qv.z, -zv.z);  ov.z = __fadd_rn(zv.z, dv.z);
            dv.w = __fadd_rn(qv.w, -zv.w);  ov.w = __fadd_rn(zv.w, dv.w);
            lsum += (double)__fmul_rn(dv.x, dv.x) + (double)__fmul_rn(dv.y, dv.y)
                  + (double)__fmul_rn(dv.z, dv.z) + (double)__fmul_rn(dv.w, dv.w);
            ob[idx] = ov;
        }
    }
    // Deterministic block reduce (double), then one exact fixed-point atomic.
    __shared__ double s_red[TPB / 32];
#pragma unroll
    for (int o = 16; o > 0; o >>= 1)
        lsum += __shfl_down_sync(0xffffffffu, lsum, o);
    if ((tid & 31) == 0) s_red[tid >> 5] = lsum;
    __syncthreads();
    if (tid == 0) {
        double t = 0.0;
#pragma unroll
        for (int i = 0; i < TPB / 32; i++) t += s_red[i];
        // fixed point 2^40: block total ~16400 -> ~1.8e16; x256 < 2^63. exact.
        u64 q = (u64)(t * 1099511627776.0 + 0.5);
        atomicAdd(&g_accum, q);
        __threadfence();
        unsigned int done = atomicAdd(&g_done, 1u);
        if (done == NBLOCKS - 1) {                // last block finalizes
            u64 total = *(volatile u64*)&g_accum;
            double s = (double)total * (1.0 / 1099511627776.0);
            float mf = (float)(s / (double)((size_t)NROWS * DIM));
            out[out_size - 1] = __fadd_rn(__fmul_rn(0.25f, mf), mf);
            *(volatile u64*)&g_accum = 0ull;      // reset for next (graph) call
            *(volatile unsigned int*)&g_done = 0u;
        }
    }
}

extern "C" void kernel_launch(void* const* d_in, const int* in_sizes, int n_in,
                              void* d_out, int out_size) {
    const float* z   = (const float*)d_in[0];
    const float* emb = (const float*)d_in[1];
    if (n_in >= 2 && in_sizes[0] == NCODES * DIM && in_sizes[1] == NROWS * DIM) {
        const float* t = z; z = emb; emb = t;   // defensive order check
    }
    float* out = (float*)d_out;

    cudaFuncSetAttribute(vq_main_kernel,
                         cudaFuncAttributeMaxDynamicSharedMemorySize, SMEM_BYTES);

    vq_prep_kernel<<<(NCODES + 127) / 128, 128>>>(emb);
    vq_main_kernel<<<NBLOCKS, TPB, SMEM_BYTES>>>(z, emb, out, out_size);
}